// round 6
// baseline (speedup 1.0000x reference)
#include <cuda_runtime.h>
#include <math.h>

#define H      512
#define IN_DIM 256
#define TSEQ   4096
#define NOUT   5
#define HC2    128          // combine grid size (must be <= 148 for co-residency)

// ---------------- static device scratch ------------------------------------
__device__ __align__(16) float g_V1[128 * H];   // level-1 vectors (from xfuse)
__device__ __align__(16) float g_V2[ 64 * H];   // level-2
__device__ __align__(16) float g_V3[ 32 * H];   // level-3 (Horner inputs)
__device__ __align__(16) float g_P[3][H * H];   // Wh^2, Wh^4, Wh^8
__device__ __align__(16) float g_w[2][H];       // Horner ping-pong
__device__ unsigned g_bar;                      // grid barrier counter

// ---------------- zeroAll: split-K targets (P2,P4,P8) + barrier -------------
__global__ void zeroAll_kernel() {
    int t = blockIdx.x * blockDim.x + threadIdx.x;   // 0 .. 196607
    float4 z = make_float4(0.f, 0.f, 0.f, 0.f);
    if (t < 3 * H * H / 4) ((float4*)g_P)[t] = z;
    if (t == 0) g_bar = 0u;
}

// ---------------- xfuse: gather + xproj + tree level 1 ----------------------
// CTA r (128 CTAs): V1[r] = y_{2r} + Wh*y_{2r+1},
//   y_k = Wx*emb[tokens[T-1-k]] + bi.
__global__ void __launch_bounds__(256, 1)
xfuse_kernel(const int* __restrict__ tokens, const float* __restrict__ emb,
             const float* __restrict__ Wi, const float* __restrict__ bi) {
    __shared__ float xe[IN_DIM], xo[IN_DIM], ve[H], vo[H];
    __shared__ int stok[2];
    int tid = threadIdx.x, w = tid >> 5, lane = tid & 31;
    int r = blockIdx.x;
    if (tid < 2) stok[tid] = tokens[TSEQ - 1 - 2 * r - tid];
    __syncthreads();
    {   // load both embedding rows
        const float* ee = emb + (size_t)stok[0] * IN_DIM;
        const float* eo = emb + (size_t)stok[1] * IN_DIM;
        xe[tid] = ee[tid];
        xo[tid] = eo[tid];
    }
    __syncthreads();
    // matvec 1: ve/vo = Wx * x + bi  (warp per output row, both vecs at once)
    for (int i = w; i < H; i += 8) {
        const float* wr = Wi + (size_t)i * 768 + lane * 8;
        float4 a0 = *(const float4*)wr;
        float4 a1 = *(const float4*)(wr + 4);
        float4 xe0 = *(const float4*)&xe[lane * 8];
        float4 xe1 = *(const float4*)&xe[lane * 8 + 4];
        float4 xo0 = *(const float4*)&xo[lane * 8];
        float4 xo1 = *(const float4*)&xo[lane * 8 + 4];
        float ae = a0.x*xe0.x + a0.y*xe0.y + a0.z*xe0.z + a0.w*xe0.w
                 + a1.x*xe1.x + a1.y*xe1.y + a1.z*xe1.z + a1.w*xe1.w;
        float ao = a0.x*xo0.x + a0.y*xo0.y + a0.z*xo0.z + a0.w*xo0.w
                 + a1.x*xo1.x + a1.y*xo1.y + a1.z*xo1.z + a1.w*xo1.w;
#pragma unroll
        for (int s = 16; s > 0; s >>= 1) {
            ae += __shfl_xor_sync(0xffffffffu, ae, s);
            ao += __shfl_xor_sync(0xffffffffu, ao, s);
        }
        if (lane == 0) {
            float b = bi[i];
            ve[i] = ae + b;
            vo[i] = ao + b;
        }
    }
    __syncthreads();
    // matvec 2: V1[r] = ve + Wh * vo  (warp per output row)
    for (int i = w; i < H; i += 8) {
        const float* hr = Wi + (size_t)i * 768 + IN_DIM;
        float acc = 0.f;
#pragma unroll
        for (int jj = 0; jj < 4; jj++) {
            float4 hv = *(const float4*)(hr + jj * 128 + lane * 4);
            float4 vv = *(const float4*)&vo[jj * 128 + lane * 4];
            acc += hv.x*vv.x + hv.y*vv.y + hv.z*vv.z + hv.w*vv.w;
        }
#pragma unroll
        for (int s = 16; s > 0; s >>= 1) acc += __shfl_xor_sync(0xffffffffu, acc, s);
        if (lane == 0) g_V1[(size_t)r * H + i] = acc + ve[i];
    }
}

// ---------------- 512^3 squaring: C += A*A (NN), split-K=4 ------------------
// tile 64x64, 256 threads, 4x4 micro, BK=32, register-prefetch pipeline.
// grid (8,8,4). C must be pre-zeroed (atomicAdd epilogue).
__global__ void __launch_bounds__(256, 2)
sqmm_kernel(const float* __restrict__ A, int lda, float* __restrict__ C) {
    __shared__ float As[32][68];
    __shared__ float Bs[32][68];
    int tid = threadIdx.x;
    int bi0 = blockIdx.x * 64;
    int bj0 = blockIdx.y * 64;
    int kbeg = blockIdx.z * 128;
    int tx = tid & 15, ty = tid >> 4;

    int arow = tid >> 2;
    int akp  = (tid & 3) * 8;
    int brow = tid >> 3;
    int bjp  = (tid & 7) * 8;

    const float* Ap = A + (size_t)(bi0 + arow) * lda + akp;
    const float* Bp = A + (size_t)brow * lda + bj0 + bjp;

    float acc[4][4];
#pragma unroll
    for (int s = 0; s < 4; s++)
#pragma unroll
        for (int t = 0; t < 4; t++) acc[s][t] = 0.f;

    float4 a0 = *(const float4*)(Ap + kbeg);
    float4 a1 = *(const float4*)(Ap + kbeg + 4);
    float4 b0 = *(const float4*)(Bp + (size_t)kbeg * lda);
    float4 b1 = *(const float4*)(Bp + (size_t)kbeg * lda + 4);

#pragma unroll
    for (int it = 0; it < 4; it++) {
        __syncthreads();
        As[akp + 0][arow] = a0.x; As[akp + 1][arow] = a0.y;
        As[akp + 2][arow] = a0.z; As[akp + 3][arow] = a0.w;
        As[akp + 4][arow] = a1.x; As[akp + 5][arow] = a1.y;
        As[akp + 6][arow] = a1.z; As[akp + 7][arow] = a1.w;
        *(float4*)&Bs[brow][bjp]     = b0;
        *(float4*)&Bs[brow][bjp + 4] = b1;
        __syncthreads();
        if (it < 3) {
            int kt = kbeg + (it + 1) * 32;
            a0 = *(const float4*)(Ap + kt);
            a1 = *(const float4*)(Ap + kt + 4);
            b0 = *(const float4*)(Bp + (size_t)kt * lda);
            b1 = *(const float4*)(Bp + (size_t)kt * lda + 4);
        }
#pragma unroll
        for (int k = 0; k < 32; k++) {
            float4 a = *(const float4*)&As[k][ty * 4];
            float4 b = *(const float4*)&Bs[k][tx * 4];
            acc[0][0] += a.x*b.x; acc[0][1] += a.x*b.y; acc[0][2] += a.x*b.z; acc[0][3] += a.x*b.w;
            acc[1][0] += a.y*b.x; acc[1][1] += a.y*b.y; acc[1][2] += a.y*b.z; acc[1][3] += a.y*b.w;
            acc[2][0] += a.z*b.x; acc[2][1] += a.z*b.y; acc[2][2] += a.z*b.z; acc[2][3] += a.z*b.w;
            acc[3][0] += a.w*b.x; acc[3][1] += a.w*b.y; acc[3][2] += a.w*b.z; acc[3][3] += a.w*b.w;
        }
    }
#pragma unroll
    for (int s = 0; s < 4; s++)
#pragma unroll
        for (int t = 0; t < 4; t++)
            atomicAdd(&C[(size_t)(bi0 + ty * 4 + s) * H + bj0 + tx * 4 + t], acc[s][t]);
}

// ---------------- grid barrier (release: fence + bar + atomic) --------------
__device__ __forceinline__ void gridbar(unsigned target) {
    __threadfence();
    __syncthreads();
    if (threadIdx.x == 0) {
        atomicAdd(&g_bar, 1u);
        while (*(volatile unsigned*)&g_bar < target * HC2) { }
    }
    __syncthreads();
}

// ---------------- combine: tree L2,L3 + Horner(31, P8) + readout ------------
// MUST launch with exactly HC2=128 CTAs x 256 threads, 80KB dynamic smem.
__global__ void __launch_bounds__(256, 1)
combine_kernel(const float* __restrict__ Wo, const float* __restrict__ bo,
               float* __restrict__ out) {
    extern __shared__ float smem[];
    float* Ps = smem;            // 32 rows x 512 = 64KB
    float* Vs = smem + 32 * H;   // up to 8 x 512 = 16KB
    int tid = threadIdx.x, w = tid >> 5, lane = tid & 31;
    int cta = blockIdx.x;
    int ir = cta & 15;           // i-range: rows [ir*32, ir*32+32)
    int gg = cta >> 4;           // pair group 0..7
    const float* P2 = g_P[0];
    const float* P4 = g_P[1];
    const float* P8 = g_P[2];
    unsigned phase = 0;

    // ======== stage A: V2[p] = V1[2p] + P2*V1[2p+1], p = gg*8 .. gg*8+7 =====
    for (int u = tid; u < 32 * 128; u += 256) {       // P2 tile -> smem
        int rr = u >> 7, c = (u & 127) * 4;
        *(float4*)&Ps[rr * H + c] = *(const float4*)&P2[(size_t)(ir * 32 + rr) * H + c];
    }
    for (int u = tid; u < 8 * 128; u += 256) {        // 8 odd vectors -> smem
        int pp = u >> 7, c = (u & 127) * 4;
        *(float4*)&Vs[pp * H + c] = *(const float4*)&g_V1[(size_t)(2 * (gg * 8 + pp) + 1) * H + c];
    }
    __syncthreads();
    {
        int p = gg * 8 + w;                            // warp -> pair
        for (int ii = 0; ii < 32; ii++) {
            int i = ir * 32 + ii;
            float acc = 0.f;
#pragma unroll
            for (int jj = 0; jj < 4; jj++) {
                float4 pv = *(const float4*)&Ps[ii * H + jj * 128 + lane * 4];
                float4 vv = *(const float4*)&Vs[w  * H + jj * 128 + lane * 4];
                acc += pv.x*vv.x + pv.y*vv.y + pv.z*vv.z + pv.w*vv.w;
            }
#pragma unroll
            for (int s = 16; s > 0; s >>= 1) acc += __shfl_xor_sync(0xffffffffu, acc, s);
            if (lane == 0)
                g_V2[(size_t)p * H + i] = acc + __ldg(&g_V1[(size_t)(2 * p) * H + i]);
        }
    }
    gridbar(++phase);

    // ======== stage B: V3[p] = V2[2p] + P4*V2[2p+1], p = gg*4 .. gg*4+3 =====
    __syncthreads();
    for (int u = tid; u < 32 * 128; u += 256) {       // P4 tile -> smem
        int rr = u >> 7, c = (u & 127) * 4;
        *(float4*)&Ps[rr * H + c] = *(const float4*)&P4[(size_t)(ir * 32 + rr) * H + c];
    }
    for (int u = tid; u < 4 * 128; u += 256) {        // 4 odd vectors (cross-barrier: ldcg)
        int pp = u >> 7, c = (u & 127) * 4;
        *(float4*)&Vs[pp * H + c] = __ldcg((const float4*)&g_V2[(size_t)(2 * (gg * 4 + pp) + 1) * H + c]);
    }
    __syncthreads();
    {
        int pp = w & 3, ihalf = w >> 2;
        int p = gg * 4 + pp;
        for (int t = 0; t < 16; t++) {
            int ii = ihalf * 16 + t;
            int i = ir * 32 + ii;
            float acc = 0.f;
#pragma unroll
            for (int jj = 0; jj < 4; jj++) {
                float4 pv = *(const float4*)&Ps[ii * H + jj * 128 + lane * 4];
                float4 vv = *(const float4*)&Vs[pp * H + jj * 128 + lane * 4];
                acc += pv.x*vv.x + pv.y*vv.y + pv.z*vv.z + pv.w*vv.w;
            }
#pragma unroll
            for (int s = 16; s > 0; s >>= 1) acc += __shfl_xor_sync(0xffffffffu, acc, s);
            if (lane == 0)
                g_V3[(size_t)p * H + i] = acc + __ldcg(&g_V2[(size_t)(2 * p) * H + i]);
        }
    }
    gridbar(++phase);

    // ======== Horner: w=u31; t=0..30: w = P8*w + u[30-t] ====================
    // CTA computes 4 outputs: i = cta*4 + w (warps 0..3); warps 4..7 only sync.
    for (int t = 0; t < 31; t++) {
        if (w < 4) {
            int i = cta * 4 + w;
            const float* src = (t == 0) ? &g_V3[31 * H] : g_w[(t - 1) & 1];
            const float* prow = P8 + (size_t)i * H;
            float acc = 0.f;
#pragma unroll
            for (int jj = 0; jj < 4; jj++) {
                float4 pv = *(const float4*)(prow + jj * 128 + lane * 4);
                float4 vv = __ldcg((const float4*)(src + jj * 128 + lane * 4));
                acc += pv.x*vv.x + pv.y*vv.y + pv.z*vv.z + pv.w*vv.w;
            }
#pragma unroll
            for (int s = 16; s > 0; s >>= 1) acc += __shfl_xor_sync(0xffffffffu, acc, s);
            if (lane == 0)
                g_w[t & 1][i] = acc + __ldcg(&g_V3[(size_t)(30 - t) * H + i]);
        }
        gridbar(++phase);
    }

    // ======== readout (CTA 0): logits = Wo*h + bo; log_softmax ==============
    if (cta == 0) {
        __shared__ float sl[NOUT];
        float* hsm = Vs;                        // reuse smem
        if (tid < 128)
            *(float4*)&hsm[tid * 4] = __ldcg((const float4*)&g_w[0][tid * 4]);
        __syncthreads();
        if (w < NOUT) {
            const float* wr = Wo + (size_t)w * H;
            float acc = 0.f;
#pragma unroll
            for (int jj = 0; jj < 4; jj++) {
                float4 pv = *(const float4*)(wr + jj * 128 + lane * 4);
                float4 vv = *(const float4*)&hsm[jj * 128 + lane * 4];
                acc += pv.x*vv.x + pv.y*vv.y + pv.z*vv.z + pv.w*vv.w;
            }
#pragma unroll
            for (int s = 16; s > 0; s >>= 1) acc += __shfl_xor_sync(0xffffffffu, acc, s);
            if (lane == 0) sl[w] = acc + bo[w];
        }
        __syncthreads();
        if (tid == 0) {
            float mx = sl[0];
            for (int o = 1; o < NOUT; o++) mx = fmaxf(mx, sl[o]);
            float se = 0.f;
            for (int o = 0; o < NOUT; o++) se += expf(sl[o] - mx);
            float lse = mx + logf(se);
            for (int o = 0; o < NOUT; o++) out[o] = sl[o] - lse;
        }
    }
}

// ---------------- launch (6 nodes) ------------------------------------------
extern "C" void kernel_launch(void* const* d_in, const int* in_sizes, int n_in,
                              void* d_out, int out_size) {
    const int*   tokens = (const int*)d_in[0];
    const float* emb    = (const float*)d_in[1];
    const float* Wi     = (const float*)d_in[2];
    const float* bi     = (const float*)d_in[3];
    const float* Wo     = (const float*)d_in[4];
    const float* bo     = (const float*)d_in[5];
    float* out = (float*)d_out;

    static cudaStream_t s1 = nullptr;
    static cudaEvent_t eRoot, eXF;
    static float* pP;
    static const int COMBINE_SMEM = (32 * H + 8 * H) * sizeof(float);   // 80KB
    if (!s1) {
        cudaStreamCreateWithFlags(&s1, cudaStreamNonBlocking);
        cudaEventCreateWithFlags(&eRoot, cudaEventDisableTiming);
        cudaEventCreateWithFlags(&eXF,   cudaEventDisableTiming);
        cudaGetSymbolAddress((void**)&pP, g_P);
        cudaFuncSetAttribute(combine_kernel,
                             cudaFuncAttributeMaxDynamicSharedMemorySize, COMBINE_SMEM);
    }
    const float* Wh = Wi + IN_DIM;          // Wh[i][j] = Wi[i*768 + 256 + j], ld 768
    float* P2 = pP + 0 * H * H;
    float* P4 = pP + 1 * H * H;
    float* P8 = pP + 2 * H * H;

    // fork: xfuse on s1 (record BEFORE any wait on it)
    cudaEventRecord(eRoot, 0);
    cudaStreamWaitEvent(s1, eRoot, 0);
    xfuse_kernel<<<128, 256, 0, s1>>>(tokens, emb, Wi, bi);
    cudaEventRecord(eXF, s1);

    // critical path on stream 0
    zeroAll_kernel<<<768, 256>>>();
    sqmm_kernel<<<dim3(8, 8, 4), 256>>>(Wh, 768, P2);
    sqmm_kernel<<<dim3(8, 8, 4), 256>>>(P2, 512, P4);
    sqmm_kernel<<<dim3(8, 8, 4), 256>>>(P4, 512, P8);
    cudaStreamWaitEvent(0, eXF, 0);
    combine_kernel<<<HC2, 256, COMBINE_SMEM>>>(Wo, bo, out);
}

// round 7
// speedup vs baseline: 1.1277x; 1.1277x over previous
#include <cuda_runtime.h>
#include <math.h>

#define H      512
#define IN_DIM 256
#define TSEQ   4096
#define NOUT   5
#define HC2    128          // combine grid size (<=148 for co-residency)

// ---------------- static device scratch ------------------------------------
__device__ __align__(16) float g_V1[128 * H];   // level-1 vectors (from xfuse)
__device__ __align__(16) float g_V2[ 64 * H];   // level-2
__device__ __align__(16) float g_V3[ 32 * H];   // level-3
__device__ __align__(16) float g_V4[ 16 * H];   // level-4 (Horner inputs)
__device__ __align__(16) float g_P[4][H * H];   // Wh^2, Wh^4, Wh^8, Wh^16
__device__ __align__(16) float g_w[2][H];       // Horner ping-pong
__device__ unsigned g_bar;                      // grid barrier counter

// ---------------- zeroAll: split-K targets (P2..P16) + barrier --------------
__global__ void zeroAll_kernel() {
    int t = blockIdx.x * blockDim.x + threadIdx.x;   // 0 .. 262143
    float4 z = make_float4(0.f, 0.f, 0.f, 0.f);
    if (t < 4 * H * H / 4) ((float4*)g_P)[t] = z;
    if (t == 0) g_bar = 0u;
}

// ---------------- xfuse: gather + xproj + tree level 1 ----------------------
// CTA r (128 CTAs): V1[r] = y_{2r} + Wh*y_{2r+1},  y_k = Wx*emb[tok[T-1-k]]+bi
__global__ void __launch_bounds__(256, 1)
xfuse_kernel(const int* __restrict__ tokens, const float* __restrict__ emb,
             const float* __restrict__ Wi, const float* __restrict__ bi) {
    __shared__ float xe[IN_DIM], xo[IN_DIM], ve[H], vo[H];
    __shared__ int stok[2];
    int tid = threadIdx.x, w = tid >> 5, lane = tid & 31;
    int r = blockIdx.x;
    if (tid < 2) stok[tid] = tokens[TSEQ - 1 - 2 * r - tid];
    __syncthreads();
    {
        const float* ee = emb + (size_t)stok[0] * IN_DIM;
        const float* eo = emb + (size_t)stok[1] * IN_DIM;
        xe[tid] = ee[tid];
        xo[tid] = eo[tid];
    }
    __syncthreads();
    for (int i = w; i < H; i += 8) {
        const float* wr = Wi + (size_t)i * 768 + lane * 8;
        float4 a0 = *(const float4*)wr;
        float4 a1 = *(const float4*)(wr + 4);
        float4 xe0 = *(const float4*)&xe[lane * 8];
        float4 xe1 = *(const float4*)&xe[lane * 8 + 4];
        float4 xo0 = *(const float4*)&xo[lane * 8];
        float4 xo1 = *(const float4*)&xo[lane * 8 + 4];
        float ae = a0.x*xe0.x + a0.y*xe0.y + a0.z*xe0.z + a0.w*xe0.w
                 + a1.x*xe1.x + a1.y*xe1.y + a1.z*xe1.z + a1.w*xe1.w;
        float ao = a0.x*xo0.x + a0.y*xo0.y + a0.z*xo0.z + a0.w*xo0.w
                 + a1.x*xo1.x + a1.y*xo1.y + a1.z*xo1.z + a1.w*xo1.w;
#pragma unroll
        for (int s = 16; s > 0; s >>= 1) {
            ae += __shfl_xor_sync(0xffffffffu, ae, s);
            ao += __shfl_xor_sync(0xffffffffu, ao, s);
        }
        if (lane == 0) {
            float b = bi[i];
            ve[i] = ae + b;
            vo[i] = ao + b;
        }
    }
    __syncthreads();
    for (int i = w; i < H; i += 8) {
        const float* hr = Wi + (size_t)i * 768 + IN_DIM;
        float acc = 0.f;
#pragma unroll
        for (int jj = 0; jj < 4; jj++) {
            float4 hv = *(const float4*)(hr + jj * 128 + lane * 4);
            float4 vv = *(const float4*)&vo[jj * 128 + lane * 4];
            acc += hv.x*vv.x + hv.y*vv.y + hv.z*vv.z + hv.w*vv.w;
        }
#pragma unroll
        for (int s = 16; s > 0; s >>= 1) acc += __shfl_xor_sync(0xffffffffu, acc, s);
        if (lane == 0) g_V1[(size_t)r * H + i] = acc + ve[i];
    }
}

// ---------------- 512^3 squaring: C += A*A (NN), split-K=4 ------------------
__global__ void __launch_bounds__(256, 2)
sqmm_kernel(const float* __restrict__ A, int lda, float* __restrict__ C) {
    __shared__ float As[32][68];
    __shared__ float Bs[32][68];
    int tid = threadIdx.x;
    int bi0 = blockIdx.x * 64;
    int bj0 = blockIdx.y * 64;
    int kbeg = blockIdx.z * 128;
    int tx = tid & 15, ty = tid >> 4;

    int arow = tid >> 2;
    int akp  = (tid & 3) * 8;
    int brow = tid >> 3;
    int bjp  = (tid & 7) * 8;

    const float* Ap = A + (size_t)(bi0 + arow) * lda + akp;
    const float* Bp = A + (size_t)brow * lda + bj0 + bjp;

    float acc[4][4];
#pragma unroll
    for (int s = 0; s < 4; s++)
#pragma unroll
        for (int t = 0; t < 4; t++) acc[s][t] = 0.f;

    float4 a0 = *(const float4*)(Ap + kbeg);
    float4 a1 = *(const float4*)(Ap + kbeg + 4);
    float4 b0 = *(const float4*)(Bp + (size_t)kbeg * lda);
    float4 b1 = *(const float4*)(Bp + (size_t)kbeg * lda + 4);

#pragma unroll
    for (int it = 0; it < 4; it++) {
        __syncthreads();
        As[akp + 0][arow] = a0.x; As[akp + 1][arow] = a0.y;
        As[akp + 2][arow] = a0.z; As[akp + 3][arow] = a0.w;
        As[akp + 4][arow] = a1.x; As[akp + 5][arow] = a1.y;
        As[akp + 6][arow] = a1.z; As[akp + 7][arow] = a1.w;
        *(float4*)&Bs[brow][bjp]     = b0;
        *(float4*)&Bs[brow][bjp + 4] = b1;
        __syncthreads();
        if (it < 3) {
            int kt = kbeg + (it + 1) * 32;
            a0 = *(const float4*)(Ap + kt);
            a1 = *(const float4*)(Ap + kt + 4);
            b0 = *(const float4*)(Bp + (size_t)kt * lda);
            b1 = *(const float4*)(Bp + (size_t)kt * lda + 4);
        }
#pragma unroll
        for (int k = 0; k < 32; k++) {
            float4 a = *(const float4*)&As[k][ty * 4];
            float4 b = *(const float4*)&Bs[k][tx * 4];
            acc[0][0] += a.x*b.x; acc[0][1] += a.x*b.y; acc[0][2] += a.x*b.z; acc[0][3] += a.x*b.w;
            acc[1][0] += a.y*b.x; acc[1][1] += a.y*b.y; acc[1][2] += a.y*b.z; acc[1][3] += a.y*b.w;
            acc[2][0] += a.z*b.x; acc[2][1] += a.z*b.y; acc[2][2] += a.z*b.z; acc[2][3] += a.z*b.w;
            acc[3][0] += a.w*b.x; acc[3][1] += a.w*b.y; acc[3][2] += a.w*b.z; acc[3][3] += a.w*b.w;
        }
    }
#pragma unroll
    for (int s = 0; s < 4; s++)
#pragma unroll
        for (int t = 0; t < 4; t++)
            atomicAdd(&C[(size_t)(bi0 + ty * 4 + s) * H + bj0 + tx * 4 + t], acc[s][t]);
}

// ---------------- grid barrier ----------------------------------------------
__device__ __forceinline__ void gridbar(unsigned target) {
    __threadfence();
    __syncthreads();
    if (threadIdx.x == 0) {
        atomicAdd(&g_bar, 1u);
        while (*(volatile unsigned*)&g_bar < target * HC2) { }
    }
    __syncthreads();
}

// ---------------- combine: tree L2,L3,L4 + Horner(15, P16) + readout --------
// MUST launch with exactly HC2=128 CTAs x 256 threads, 80KB dynamic smem.
__global__ void __launch_bounds__(256, 1)
combine_kernel(const float* __restrict__ Wo, const float* __restrict__ bo,
               float* __restrict__ out) {
    extern __shared__ float smem[];
    float* Ps = smem;            // 32 x 512 = 64KB
    float* Vs = smem + 32 * H;   // 8 x 512 = 16KB
    int tid = threadIdx.x, w = tid >> 5, lane = tid & 31;
    int cta = blockIdx.x;
    int ir = cta & 15;           // i-range: rows [ir*32, ir*32+32)
    int gg = cta >> 4;           // group 0..7
    const float* P2  = g_P[0];
    const float* P4  = g_P[1];
    const float* P8  = g_P[2];
    const float* P16 = g_P[3];
    unsigned phase = 0;

    // ===== stage A: V2[p] = V1[2p] + P2*V1[2p+1], p = gg*8..gg*8+7 ==========
    for (int u = tid; u < 32 * 128; u += 256) {
        int rr = u >> 7, c = (u & 127) * 4;
        *(float4*)&Ps[rr * H + c] = *(const float4*)&P2[(size_t)(ir * 32 + rr) * H + c];
    }
    for (int u = tid; u < 8 * 128; u += 256) {
        int pp = u >> 7, c = (u & 127) * 4;
        *(float4*)&Vs[pp * H + c] = *(const float4*)&g_V1[(size_t)(2 * (gg * 8 + pp) + 1) * H + c];
    }
    __syncthreads();
    {
        int p = gg * 8 + w;
        for (int ii = 0; ii < 32; ii++) {
            int i = ir * 32 + ii;
            float acc = 0.f;
#pragma unroll
            for (int jj = 0; jj < 4; jj++) {
                float4 pv = *(const float4*)&Ps[ii * H + jj * 128 + lane * 4];
                float4 vv = *(const float4*)&Vs[w  * H + jj * 128 + lane * 4];
                acc += pv.x*vv.x + pv.y*vv.y + pv.z*vv.z + pv.w*vv.w;
            }
#pragma unroll
            for (int s = 16; s > 0; s >>= 1) acc += __shfl_xor_sync(0xffffffffu, acc, s);
            if (lane == 0)
                g_V2[(size_t)p * H + i] = acc + __ldg(&g_V1[(size_t)(2 * p) * H + i]);
        }
    }
    gridbar(++phase);

    // ===== stage B: V3[p] = V2[2p] + P4*V2[2p+1], p = gg*4..gg*4+3 ==========
    __syncthreads();
    for (int u = tid; u < 32 * 128; u += 256) {
        int rr = u >> 7, c = (u & 127) * 4;
        *(float4*)&Ps[rr * H + c] = *(const float4*)&P4[(size_t)(ir * 32 + rr) * H + c];
    }
    for (int u = tid; u < 4 * 128; u += 256) {
        int pp = u >> 7, c = (u & 127) * 4;
        *(float4*)&Vs[pp * H + c] = __ldcg((const float4*)&g_V2[(size_t)(2 * (gg * 4 + pp) + 1) * H + c]);
    }
    __syncthreads();
    {
        int pp = w & 3, ihalf = w >> 2;
        int p = gg * 4 + pp;
        for (int t = 0; t < 16; t++) {
            int ii = ihalf * 16 + t;
            int i = ir * 32 + ii;
            float acc = 0.f;
#pragma unroll
            for (int jj = 0; jj < 4; jj++) {
                float4 pv = *(const float4*)&Ps[ii * H + jj * 128 + lane * 4];
                float4 vv = *(const float4*)&Vs[pp * H + jj * 128 + lane * 4];
                acc += pv.x*vv.x + pv.y*vv.y + pv.z*vv.z + pv.w*vv.w;
            }
#pragma unroll
            for (int s = 16; s > 0; s >>= 1) acc += __shfl_xor_sync(0xffffffffu, acc, s);
            if (lane == 0)
                g_V3[(size_t)p * H + i] = acc + __ldcg(&g_V2[(size_t)(2 * p) * H + i]);
        }
    }
    gridbar(++phase);

    // ===== stage C: V4[p] = V3[2p] + P8*V3[2p+1], p = gg*2..gg*2+1 ==========
    __syncthreads();
    for (int u = tid; u < 32 * 128; u += 256) {
        int rr = u >> 7, c = (u & 127) * 4;
        *(float4*)&Ps[rr * H + c] = *(const float4*)&P8[(size_t)(ir * 32 + rr) * H + c];
    }
    for (int u = tid; u < 2 * 128; u += 256) {
        int pp = u >> 7, c = (u & 127) * 4;
        *(float4*)&Vs[pp * H + c] = __ldcg((const float4*)&g_V3[(size_t)(2 * (gg * 2 + pp) + 1) * H + c]);
    }
    __syncthreads();
    {
        int pp = w & 1, iq = w >> 1;                   // 2 pairs, 4 warps each
        int p = gg * 2 + pp;
        for (int t = 0; t < 8; t++) {
            int ii = iq * 8 + t;
            int i = ir * 32 + ii;
            float acc = 0.f;
#pragma unroll
            for (int jj = 0; jj < 4; jj++) {
                float4 pv = *(const float4*)&Ps[ii * H + jj * 128 + lane * 4];
                float4 vv = *(const float4*)&Vs[pp * H + jj * 128 + lane * 4];
                acc += pv.x*vv.x + pv.y*vv.y + pv.z*vv.z + pv.w*vv.w;
            }
#pragma unroll
            for (int s = 16; s > 0; s >>= 1) acc += __shfl_xor_sync(0xffffffffu, acc, s);
            if (lane == 0)
                g_V4[(size_t)p * H + i] = acc + __ldcg(&g_V3[(size_t)(2 * p) * H + i]);
        }
    }
    gridbar(++phase);

    // ===== cache this CTA's 4 P16 rows in smem (reused 15x) =================
    __syncthreads();
    for (int u = tid; u < 4 * 128; u += 256) {
        int rr = u >> 7, c = (u & 127) * 4;
        *(float4*)&Ps[rr * H + c] = *(const float4*)&P16[(size_t)(cta * 4 + rr) * H + c];
    }
    __syncthreads();

    // ===== Horner: w=u15; t=0..14: w = P16*w + u[14-t] ======================
    for (int t = 0; t < 15; t++) {
        if (w < 4) {
            int i = cta * 4 + w;
            const float* src = (t == 0) ? &g_V4[15 * H] : g_w[(t - 1) & 1];
            float acc = 0.f;
#pragma unroll
            for (int jj = 0; jj < 4; jj++) {
                float4 pv = *(const float4*)&Ps[w * H + jj * 128 + lane * 4];
                float4 vv = __ldcg((const float4*)(src + jj * 128 + lane * 4));
                acc += pv.x*vv.x + pv.y*vv.y + pv.z*vv.z + pv.w*vv.w;
            }
#pragma unroll
            for (int s = 16; s > 0; s >>= 1) acc += __shfl_xor_sync(0xffffffffu, acc, s);
            if (lane == 0)
                g_w[t & 1][i] = acc + __ldcg(&g_V4[(size_t)(14 - t) * H + i]);
        }
        gridbar(++phase);
    }

    // ===== readout (CTA 0): h in g_w[0] (t=14) ==============================
    if (cta == 0) {
        __shared__ float sl[NOUT];
        float* hsm = Vs;
        if (tid < 128)
            *(float4*)&hsm[tid * 4] = __ldcg((const float4*)&g_w[0][tid * 4]);
        __syncthreads();
        if (w < NOUT) {
            const float* wr = Wo + (size_t)w * H;
            float acc = 0.f;
#pragma unroll
            for (int jj = 0; jj < 4; jj++) {
                float4 pv = *(const float4*)(wr + jj * 128 + lane * 4);
                float4 vv = *(const float4*)&hsm[jj * 128 + lane * 4];
                acc += pv.x*vv.x + pv.y*vv.y + pv.z*vv.z + pv.w*vv.w;
            }
#pragma unroll
            for (int s = 16; s > 0; s >>= 1) acc += __shfl_xor_sync(0xffffffffu, acc, s);
            if (lane == 0) sl[w] = acc + bo[w];
        }
        __syncthreads();
        if (tid == 0) {
            float mx = sl[0];
            for (int o = 1; o < NOUT; o++) mx = fmaxf(mx, sl[o]);
            float se = 0.f;
            for (int o = 0; o < NOUT; o++) se += expf(sl[o] - mx);
            float lse = mx + logf(se);
            for (int o = 0; o < NOUT; o++) out[o] = sl[o] - lse;
        }
    }
}

// ---------------- launch (7 nodes) ------------------------------------------
extern "C" void kernel_launch(void* const* d_in, const int* in_sizes, int n_in,
                              void* d_out, int out_size) {
    const int*   tokens = (const int*)d_in[0];
    const float* emb    = (const float*)d_in[1];
    const float* Wi     = (const float*)d_in[2];
    const float* bi     = (const float*)d_in[3];
    const float* Wo     = (const float*)d_in[4];
    const float* bo     = (const float*)d_in[5];
    float* out = (float*)d_out;

    static cudaStream_t s1 = nullptr;
    static cudaEvent_t eRoot, eXF;
    static float* pP;
    static const int COMBINE_SMEM = (32 * H + 8 * H) * sizeof(float);   // 80KB
    if (!s1) {
        cudaStreamCreateWithFlags(&s1, cudaStreamNonBlocking);
        cudaEventCreateWithFlags(&eRoot, cudaEventDisableTiming);
        cudaEventCreateWithFlags(&eXF,   cudaEventDisableTiming);
        cudaGetSymbolAddress((void**)&pP, g_P);
        cudaFuncSetAttribute(combine_kernel,
                             cudaFuncAttributeMaxDynamicSharedMemorySize, COMBINE_SMEM);
    }
    const float* Wh = Wi + IN_DIM;          // ld 768
    float* P2  = pP + 0 * H * H;
    float* P4  = pP + 1 * H * H;
    float* P8  = pP + 2 * H * H;
    float* P16 = pP + 3 * H * H;

    // fork: xfuse on s1 (record before any wait)
    cudaEventRecord(eRoot, 0);
    cudaStreamWaitEvent(s1, eRoot, 0);
    xfuse_kernel<<<128, 256, 0, s1>>>(tokens, emb, Wi, bi);
    cudaEventRecord(eXF, s1);

    // critical path on stream 0
    zeroAll_kernel<<<1024, 256>>>();
    sqmm_kernel<<<dim3(8, 8, 4), 256>>>(Wh,  768, P2);
    sqmm_kernel<<<dim3(8, 8, 4), 256>>>(P2,  512, P4);
    sqmm_kernel<<<dim3(8, 8, 4), 256>>>(P4,  512, P8);
    sqmm_kernel<<<dim3(8, 8, 4), 256>>>(P8,  512, P16);
    cudaStreamWaitEvent(0, eXF, 0);
    combine_kernel<<<HC2, 256, COMBINE_SMEM>>>(Wo, bo, out);
}